// round 10
// baseline (speedup 1.0000x reference)
#include <cuda_runtime.h>
#include <cstdint>

#define D_MODEL 1024
#define NHEADS  16
#define HDIM    64
#define BATCH   2
#define SEQ     2048
#define MROWS   (BATCH*SEQ)   // 4096

// Interleave map within 8-groups: position p holds original index perm(p) =
// [0,4,1,5,2,6,3,7]; writer maps original c -> position q(c) = ((c&3)<<1)|(c>>2).
// Readers then find (k, k+4) at adjacent positions (2k', 2k'+1) -> LDS.64.

// ---------------- scratch (device globals: no allocations allowed) ----------
__device__ float g_Q[MROWS*D_MODEL];            // [row][dim'] dims interleaved
__device__ float g_K[MROWS*D_MODEL];            // [row][dim'] dims interleaved
__device__ float g_Vt[MROWS*D_MODEL];           // [b][dim][key'] keys interleaved
__device__ float g_ctx[MROWS*D_MODEL];          // [row][dim'] dims interleaved
__device__ float g_x1[MROWS*D_MODEL];           // tf32, k-cols interleaved
__device__ float g_x2[MROWS*D_MODEL];           // tf32, k-cols interleaved
// weights transposed to K-major [n][k'] with k-interleave, tf32
__device__ float g_WqT[D_MODEL*D_MODEL];
__device__ float g_WkT[D_MODEL*D_MODEL];
__device__ float g_WvT[D_MODEL*D_MODEL];
__device__ float g_WoT[D_MODEL*D_MODEL];

// ---------------- helpers ---------------------------------------------------
__device__ __forceinline__ float to_tf32(float x){
    unsigned u;
    asm("cvt.rna.tf32.f32 %0, %1;" : "=r"(u) : "f"(x));
    return __uint_as_float(u);
}

__device__ __forceinline__ void mma8(float c[4], const unsigned a[4], const unsigned b[2]){
    asm volatile(
        "mma.sync.aligned.m16n8k8.row.col.f32.tf32.tf32.f32 "
        "{%0,%1,%2,%3}, {%4,%5,%6,%7}, {%8,%9}, {%0,%1,%2,%3};\n"
        : "+f"(c[0]), "+f"(c[1]), "+f"(c[2]), "+f"(c[3])
        : "r"(a[0]), "r"(a[1]), "r"(a[2]), "r"(a[3]),
          "r"(b[0]), "r"(b[1]));
}

__device__ __forceinline__ void cpa16(float* dst, const float* src){
    unsigned s = (unsigned)__cvta_generic_to_shared(dst);
    asm volatile("cp.async.cg.shared.global [%0], [%1], 16;\n" :: "r"(s), "l"(src));
}
#define CP_COMMIT() asm volatile("cp.async.commit_group;\n" ::: "memory")
#define CP_WAIT0()  asm volatile("cp.async.wait_group 0;\n" ::: "memory")

// ---------------- pre-pass: activations tf32 + k-interleave ------------------
__global__ void __launch_bounds__(256) preround_x(
    const float* __restrict__ x1, const float* __restrict__ x2)
{
    const float* src = blockIdx.z ? x2 : x1;
    float* dst       = blockIdx.z ? g_x2 : g_x1;
    const int ng = MROWS*D_MODEL/8;
    for (int gi = blockIdx.x*blockDim.x + threadIdx.x; gi < ng; gi += gridDim.x*blockDim.x){
        float4 lo = ((const float4*)src)[gi*2];
        float4 hi = ((const float4*)src)[gi*2+1];
        float4 o0 = make_float4(to_tf32(lo.x), to_tf32(hi.x), to_tf32(lo.y), to_tf32(hi.y));
        float4 o1 = make_float4(to_tf32(lo.z), to_tf32(hi.z), to_tf32(lo.w), to_tf32(hi.w));
        ((float4*)dst)[gi*2]   = o0;
        ((float4*)dst)[gi*2+1] = o1;
    }
}

// ---------------- pre-pass: weights -> tf32, transposed, k-interleaved -------
__global__ void __launch_bounds__(256) transpose_w(
    const float* __restrict__ Wq, const float* __restrict__ Wk,
    const float* __restrict__ Wv, const float* __restrict__ Wo)
{
    __shared__ float tile[32][33];
    const float* W; float* WT;
    switch (blockIdx.z){
        case 0: W = Wq; WT = g_WqT; break;
        case 1: W = Wk; WT = g_WkT; break;
        case 2: W = Wv; WT = g_WvT; break;
        default:W = Wo; WT = g_WoT; break;
    }
    const int tx = threadIdx.x, ty = threadIdx.y;
    const int n0 = blockIdx.x*32, k0 = blockIdx.y*32;
#pragma unroll
    for (int i=0;i<4;i++)
        tile[ty+8*i][tx] = to_tf32(W[(size_t)(k0+ty+8*i)*D_MODEL + n0+tx]);
    __syncthreads();
    // out k position within 8-group interleaved: kpos = (k&24) | q(k&7)
    const int kpos = (tx & 24) | (((tx&3)<<1) | ((tx&7)>>2));
#pragma unroll
    for (int i=0;i<4;i++)
        WT[(size_t)(n0+ty+8*i)*D_MODEL + k0 + kpos] = tile[tx][ty+8*i];
}

// ---------------- tiled tf32 GEMM (cp.async 2-stage, all-LDS.64 frags) -------
// C = (A @ W + b) * oscale. A tf32 k-interleaved [m][k']; WT tf32 K-major
// k-interleaved [n][k']. BM=128 BN=128 BK=32, 256 threads (8 warps as 2x4).
// MODE: 0 = plain f32 out; 1 = tf32 + col-interleave; 2 = tf32 transposed V.
#define AS_LD 40            // 40 % 32 == 8 -> float2 frag banks (8g+2tg)/phase: conflict-free
#define BS_LD 40
#define AS_SZ (128*AS_LD)   // 5120 floats
#define BS_SZ (128*BS_LD)   // 5120 floats
#define GEMM_SMEM (2*(AS_SZ + BS_SZ)*4)   // 81920 bytes
#define KT32 (D_MODEL/32)

template<int MODE>
__device__ __forceinline__ void gemm_bias(const float* __restrict__ A,
                                          const float* __restrict__ WT,
                                          const float* __restrict__ bias,
                                          float* __restrict__ C,
                                          const float oscale)
{
    extern __shared__ float sm[];
    float* As = sm;               // 2 buffers
    float* Bs = sm + 2*AS_SZ;

    const int tid  = threadIdx.x;
    const int lane = tid & 31;
    const int warp = tid >> 5;
    const int g    = lane >> 2;
    const int tg   = lane & 3;
    const int wm   = warp >> 2;   // 0..1
    const int wn   = warp & 3;    // 0..3
    const int bm   = blockIdx.y * 128;
    const int bn   = blockIdx.x * 128;

    float c[4][4][4];
#pragma unroll
    for (int i=0;i<4;i++)
#pragma unroll
        for (int j=0;j<4;j++){ c[i][j][0]=0.f;c[i][j][1]=0.f;c[i][j][2]=0.f;c[i][j][3]=0.f; }

    auto fill = [&](int t, int s){
        float* As_ = As + s*AS_SZ;
        float* Bs_ = Bs + s*BS_SZ;
        const int k0 = t*32;
#pragma unroll
        for (int i=0;i<4;i++){
            int f = tid + i*256;
            int row = f>>3, c16 = (f&7)<<2;
            cpa16(As_ + row*AS_LD + c16,
                  A  + (size_t)(bm + row)*D_MODEL + k0 + c16);
            cpa16(Bs_ + row*BS_LD + c16,
                  WT + (size_t)(bn + row)*D_MODEL + k0 + c16);
        }
        CP_COMMIT();
    };

    fill(0, 0);

    for (int t = 0; t < KT32; ++t){
        CP_WAIT0();
        __syncthreads();
        if (t+1 < KT32) fill(t+1, (t+1)&1);

        const float* Asc = As + (t&1)*AS_SZ;
        const float* Bsc = Bs + (t&1)*BS_SZ;
#pragma unroll
        for (int kt=0;kt<4;kt++){
            unsigned af[4][4], bf[4][2];
#pragma unroll
            for (int i=0;i<4;i++){
                const float* p = Asc + (wm*64 + i*16 + g)*AS_LD + kt*8 + 2*tg;
                float2 v0 = *(const float2*)p;
                float2 v1 = *(const float2*)(p + 8*AS_LD);
                af[i][0]=__float_as_uint(v0.x);
                af[i][1]=__float_as_uint(v1.x);
                af[i][2]=__float_as_uint(v0.y);
                af[i][3]=__float_as_uint(v1.y);
            }
#pragma unroll
            for (int j=0;j<4;j++){
                float2 v = *(const float2*)(Bsc + (wn*32 + j*8 + g)*BS_LD + kt*8 + 2*tg);
                bf[j][0]=__float_as_uint(v.x);
                bf[j][1]=__float_as_uint(v.y);
            }
#pragma unroll
            for (int i=0;i<4;i++)
#pragma unroll
                for (int j=0;j<4;j++)
                    mma8(c[i][j], af[i], bf[j]);
        }
    }
    __syncthreads();

    // epilogue
#pragma unroll
    for (int i=0;i<4;i++){
        const int r0 = bm + wm*64 + i*16 + g;
#pragma unroll
        for (int j=0;j<4;j++){
            const int gb  = bn + wn*32 + j*8;
            const int col = gb + 2*tg;
            const float b0 = bias[col], b1 = bias[col+1];
            float v00=(c[i][j][0]+b0)*oscale, v01=(c[i][j][1]+b1)*oscale;
            float v10=(c[i][j][2]+b0)*oscale, v11=(c[i][j][3]+b1)*oscale;
            if (MODE == 0){
                *(float2*)(C + (size_t)r0*D_MODEL + col)     = make_float2(v00, v01);
                *(float2*)(C + (size_t)(r0+8)*D_MODEL + col) = make_float2(v10, v11);
            } else if (MODE == 1){
                const int pos = ((tg&1)<<2) | (tg>>1);   // q(2tg); q(2tg+1)=pos+2
                C[(size_t)r0*D_MODEL + gb + pos]       = to_tf32(v00);
                C[(size_t)r0*D_MODEL + gb + pos + 2]   = to_tf32(v01);
                C[(size_t)(r0+8)*D_MODEL + gb + pos]   = to_tf32(v10);
                C[(size_t)(r0+8)*D_MODEL + gb + pos+2] = to_tf32(v11);
            } else {
                // transposed V: C[b][dim][key'], keys interleaved within 8-groups
                const int bidx = r0 >> 11;
                const int s0   = r0 & 2047;
                const int key0 = (s0 & ~7) | (((g&3)<<1) | (g>>2));   // q(g)
                const size_t base = ((size_t)bidx*D_MODEL + col)*SEQ;
                C[base + key0]           = to_tf32(v00);
                C[base + SEQ + key0]     = to_tf32(v01);
                C[base + key0 + 8]       = to_tf32(v10);
                C[base + SEQ + key0 + 8] = to_tf32(v11);
            }
        }
    }
}

__global__ void __launch_bounds__(256, 2) qkv_kernel(
    const float* __restrict__ bq, const float* __restrict__ bk,
    const float* __restrict__ bv)
{
    // Q carries 1/sqrt(HDIM)=0.125 (exact pow2, commutes with tf32 rounding).
    if      (blockIdx.z == 0) gemm_bias<1>(g_x1, g_WqT, bq, g_Q, 0.125f);
    else if (blockIdx.z == 1) gemm_bias<1>(g_x2, g_WkT, bk, g_K, 1.0f);
    else                      gemm_bias<2>(g_x2, g_WvT, bv, g_Vt, 1.0f);
}

__global__ void __launch_bounds__(256, 2) oproj_kernel(
    const float* __restrict__ bo, float* __restrict__ out)
{
    gemm_bias<0>(g_ctx, g_WoT, bo, out, 1.0f);
}

// ---------------- flash attention (UNCHANGED from R8 winner) -----------------
#define QP_LD 72   // 72 % 32 == 8 -> float2 frag banks 8g+2tg conflict-free
#define K_LD  72
#define V_LD  72
#define KV_BUF (64*K_LD + 64*V_LD)   // 9216 floats per stage
#define ATTN_SMEM ((128*QP_LD + 2*KV_BUF)*4)   // 110592 bytes
#define NT (SEQ/64)

__global__ void __launch_bounds__(256, 2) attn_kernel()
{
    extern __shared__ float sm[];
    float* Qs = sm;                       // 128*QP_LD ; reused as Ps

    const int tid  = threadIdx.x;
    const int lane = tid & 31;
    const int warp = tid >> 5;
    const int g    = lane >> 2;
    const int tg   = lane & 3;
    const int b    = blockIdx.y >> 4;
    const int h    = blockIdx.y & 15;
    const int q0   = blockIdx.x * 128;

    const float* Kb = g_K  + (size_t)(b*SEQ)*D_MODEL + h*HDIM;
    const float* Vb = g_Vt + ((size_t)(b*D_MODEL) + h*HDIM)*SEQ;  // rows=dims

    const int cr[4] = { (tid)>>4, (tid+256)>>4, (tid+512)>>4, (tid+768)>>4 };
    const int cc    = (tid & 15) << 2;

    {
        float* Ks0 = sm + 128*QP_LD;
        float* Vs0 = Ks0 + 64*K_LD;
#pragma unroll
        for (int i=0;i<4;i++){
            int r = cr[i];
            cpa16(Ks0 + r*K_LD + cc, Kb + (size_t)r*D_MODEL + cc);
            cpa16(Vs0 + r*V_LD + cc, Vb + (size_t)r*SEQ + cc);
        }
        CP_COMMIT();
    }

    const float* Qg = g_Q + (size_t)(b*SEQ + q0)*D_MODEL + h*HDIM;
#pragma unroll
    for (int i=0;i<8;i++){
        int f = tid + i*256;
        int r = f >> 4, c = (f & 15) << 2;
        *(float4*)(Qs + r*QP_LD + c) = *(const float4*)(Qg + (size_t)r*D_MODEL + c);
    }
    __syncthreads();

    unsigned qa[8][4];
#pragma unroll
    for (int kt=0;kt<8;kt++){
        const float* p = Qs + (warp*16 + g)*QP_LD + kt*8 + 2*tg;
        float2 v0 = *(const float2*)p;
        float2 v1 = *(const float2*)(p + 8*QP_LD);
        qa[kt][0]=__float_as_uint(v0.x);
        qa[kt][1]=__float_as_uint(v1.x);
        qa[kt][2]=__float_as_uint(v0.y);
        qa[kt][3]=__float_as_uint(v1.y);
    }

    float ctx[8][4];
#pragma unroll
    for (int n=0;n<8;n++){ ctx[n][0]=0.f;ctx[n][1]=0.f;ctx[n][2]=0.f;ctx[n][3]=0.f; }
    const float NEG = -1e30f;
    float m0=NEG, m1=NEG, l0=0.f, l1=0.f;
    float* Ps = Qs;
    const int ppos = ((tg&1)<<2) | (tg>>1);   // q(2tg)

    for (int t=0; t<NT; ++t){
        CP_WAIT0();
        __syncthreads();

        if (t+1 < NT){
            float* Ksn = sm + 128*QP_LD + ((t+1)&1)*KV_BUF;
            float* Vsn = Ksn + 64*K_LD;
            const float* Kg = Kb + (size_t)(t+1)*64*D_MODEL;
            const float* Vg = Vb + (t+1)*64;
#pragma unroll
            for (int i=0;i<4;i++){
                int r = cr[i];
                cpa16(Ksn + r*K_LD + cc, Kg + (size_t)r*D_MODEL + cc);
                cpa16(Vsn + r*V_LD + cc, Vg + (size_t)r*SEQ + cc);
            }
            CP_COMMIT();
        }

        const float* Ks = sm + 128*QP_LD + (t&1)*KV_BUF;
        const float* Vs = Ks + 64*K_LD;

        float s[8][4];
#pragma unroll
        for (int n=0;n<8;n++){ s[n][0]=0.f;s[n][1]=0.f;s[n][2]=0.f;s[n][3]=0.f; }
#pragma unroll
        for (int nt=0;nt<8;nt++){
#pragma unroll
            for (int kt=0;kt<8;kt++){
                float2 kv = *(const float2*)(Ks + (nt*8 + g)*K_LD + kt*8 + 2*tg);
                unsigned bf[2] = { __float_as_uint(kv.x), __float_as_uint(kv.y) };
                mma8(s[nt], qa[kt], bf);
            }
        }

        float rm0=NEG, rm1=NEG;
#pragma unroll
        for (int n=0;n<8;n++){
            rm0 = fmaxf(rm0, fmaxf(s[n][0], s[n][1]));
            rm1 = fmaxf(rm1, fmaxf(s[n][2], s[n][3]));
        }
        rm0 = fmaxf(rm0, __shfl_xor_sync(0xffffffffu, rm0, 1));
        rm0 = fmaxf(rm0, __shfl_xor_sync(0xffffffffu, rm0, 2));
        rm1 = fmaxf(rm1, __shfl_xor_sync(0xffffffffu, rm1, 1));
        rm1 = fmaxf(rm1, __shfl_xor_sync(0xffffffffu, rm1, 2));
        const float mn0 = fmaxf(m0, rm0), mn1 = fmaxf(m1, rm1);
        const float a0 = __expf(m0 - mn0), a1 = __expf(m1 - mn1);
        float rs0=0.f, rs1=0.f;
#pragma unroll
        for (int n=0;n<8;n++){
            s[n][0]=__expf(s[n][0]-mn0); s[n][1]=__expf(s[n][1]-mn0);
            s[n][2]=__expf(s[n][2]-mn1); s[n][3]=__expf(s[n][3]-mn1);
            rs0 += s[n][0]+s[n][1];
            rs1 += s[n][2]+s[n][3];
        }
        rs0 += __shfl_xor_sync(0xffffffffu, rs0, 1);
        rs0 += __shfl_xor_sync(0xffffffffu, rs0, 2);
        rs1 += __shfl_xor_sync(0xffffffffu, rs1, 1);
        rs1 += __shfl_xor_sync(0xffffffffu, rs1, 2);
        l0 = a0*l0 + rs0;  l1 = a1*l1 + rs1;
        m0 = mn0;          m1 = mn1;
#pragma unroll
        for (int n=0;n<8;n++){
            ctx[n][0]*=a0; ctx[n][1]*=a0; ctx[n][2]*=a1; ctx[n][3]*=a1;
        }

        {
            const int r = warp*16 + g;
#pragma unroll
            for (int n=0;n<8;n++){
                float* p0 = Ps + r*QP_LD + n*8 + ppos;
                p0[0] = to_tf32(s[n][0]);
                p0[2] = to_tf32(s[n][1]);
                float* p1 = Ps + (r+8)*QP_LD + n*8 + ppos;
                p1[0] = to_tf32(s[n][2]);
                p1[2] = to_tf32(s[n][3]);
            }
        }
        __syncwarp();

#pragma unroll
        for (int kt=0;kt<8;kt++){
            unsigned pa[4];
            const float* pp = Ps + (warp*16+g)*QP_LD + kt*8 + 2*tg;
            float2 v0 = *(const float2*)pp;
            float2 v1 = *(const float2*)(pp + 8*QP_LD);
            pa[0]=__float_as_uint(v0.x);
            pa[1]=__float_as_uint(v1.x);
            pa[2]=__float_as_uint(v0.y);
            pa[3]=__float_as_uint(v1.y);
#pragma unroll
            for (int nt=0;nt<8;nt++){
                float2 vv = *(const float2*)(Vs + (nt*8 + g)*V_LD + kt*8 + 2*tg);
                unsigned bf[2] = { __float_as_uint(vv.x), __float_as_uint(vv.y) };
                mma8(ctx[nt], pa, bf);
            }
        }
    }

    const float il0 = 1.f/l0, il1 = 1.f/l1;
    const int r = b*SEQ + q0 + warp*16 + g;
#pragma unroll
    for (int n=0;n<8;n++){
        const int gb = h*HDIM + n*8;
        g_ctx[(size_t)r*D_MODEL + gb + ppos]       = to_tf32(ctx[n][0]*il0);
        g_ctx[(size_t)r*D_MODEL + gb + ppos + 2]   = to_tf32(ctx[n][1]*il0);
        g_ctx[(size_t)(r+8)*D_MODEL + gb + ppos]   = to_tf32(ctx[n][2]*il1);
        g_ctx[(size_t)(r+8)*D_MODEL + gb + ppos+2] = to_tf32(ctx[n][3]*il1);
    }
}

// ---------------- launch ----------------------------------------------------
extern "C" void kernel_launch(void* const* d_in, const int* in_sizes, int n_in,
                              void* d_out, int out_size)
{
    (void)in_sizes; (void)n_in; (void)out_size;
    const float* x1 = (const float*)d_in[0];
    const float* x2 = (const float*)d_in[1];
    const float* Wq = (const float*)d_in[2];
    const float* bq = (const float*)d_in[3];
    const float* Wk = (const float*)d_in[4];
    const float* bk = (const float*)d_in[5];
    const float* Wv = (const float*)d_in[6];
    const float* bv = (const float*)d_in[7];
    const float* Wo = (const float*)d_in[8];
    const float* bo = (const float*)d_in[9];
    float* out = (float*)d_out;

    cudaFuncSetAttribute(qkv_kernel,  cudaFuncAttributeMaxDynamicSharedMemorySize, GEMM_SMEM);
    cudaFuncSetAttribute(oproj_kernel,cudaFuncAttributeMaxDynamicSharedMemorySize, GEMM_SMEM);
    cudaFuncSetAttribute(attn_kernel, cudaFuncAttributeMaxDynamicSharedMemorySize, ATTN_SMEM);

    preround_x<<<dim3(1024, 1, 2), 256>>>(x1, x2);
    transpose_w<<<dim3(32, 32, 4), dim3(32, 8)>>>(Wq, Wk, Wv, Wo);
    qkv_kernel<<<dim3(D_MODEL/128, MROWS/128, 3), 256, GEMM_SMEM>>>(bq, bk, bv);
    attn_kernel<<<dim3(SEQ/128, BATCH*NHEADS), 256, ATTN_SMEM>>>();
    oproj_kernel<<<dim3(D_MODEL/128, MROWS/128), 256, GEMM_SMEM>>>(bo, out);
}

// round 12
// speedup vs baseline: 1.0700x; 1.0700x over previous
#include <cuda_runtime.h>
#include <cstdint>

#define D_MODEL 1024
#define NHEADS  16
#define HDIM    64
#define BATCH   2
#define SEQ     2048
#define MROWS   (BATCH*SEQ)   // 4096

// Interleave map within 8-groups: position p holds original index perm(p) =
// [0,4,1,5,2,6,3,7]; writer maps original c -> position q(c) = ((c&3)<<1)|(c>>2).
// Readers then find (k, k+4) at adjacent positions (2k', 2k'+1) -> LDS.64.

// ---------------- scratch (device globals: no allocations allowed) ----------
__device__ float g_Q[MROWS*D_MODEL];            // [row][dim'] dims interleaved
__device__ float g_K[MROWS*D_MODEL];            // [row][dim'] dims interleaved
__device__ float g_Vt[MROWS*D_MODEL];           // [b][dim][key] keys PLAIN
__device__ float g_ctx[MROWS*D_MODEL];          // [row][dim'] dims interleaved
__device__ float g_x1[MROWS*D_MODEL];           // tf32, k-cols interleaved
__device__ float g_x2[MROWS*D_MODEL];           // tf32, k-cols interleaved
__device__ float g_Wq[D_MODEL*D_MODEL];         // tf32, plain
__device__ float g_Wk[D_MODEL*D_MODEL];
__device__ float g_Wv[D_MODEL*D_MODEL];
__device__ float g_Wo[D_MODEL*D_MODEL];

// ---------------- helpers ---------------------------------------------------
__device__ __forceinline__ float to_tf32(float x){
    unsigned u;
    asm("cvt.rna.tf32.f32 %0, %1;" : "=r"(u) : "f"(x));
    return __uint_as_float(u);
}

__device__ __forceinline__ void mma8(float c[4], const unsigned a[4], const unsigned b[2]){
    asm volatile(
        "mma.sync.aligned.m16n8k8.row.col.f32.tf32.tf32.f32 "
        "{%0,%1,%2,%3}, {%4,%5,%6,%7}, {%8,%9}, {%0,%1,%2,%3};\n"
        : "+f"(c[0]), "+f"(c[1]), "+f"(c[2]), "+f"(c[3])
        : "r"(a[0]), "r"(a[1]), "r"(a[2]), "r"(a[3]),
          "r"(b[0]), "r"(b[1]));
}

__device__ __forceinline__ void cpa16(float* dst, const float* src){
    unsigned s = (unsigned)__cvta_generic_to_shared(dst);
    asm volatile("cp.async.cg.shared.global [%0], [%1], 16;\n" :: "r"(s), "l"(src));
}
#define CP_COMMIT() asm volatile("cp.async.commit_group;\n" ::: "memory")
#define CP_WAIT0()  asm volatile("cp.async.wait_group 0;\n" ::: "memory")

// ---------------- pre-round pass --------------------------------------------
// z 0/1: x1/x2 -> tf32 with k-col interleave. z 2..5: weights -> tf32 plain.
__global__ void __launch_bounds__(256) preround_kernel(
    const float* __restrict__ x1, const float* __restrict__ x2,
    const float* __restrict__ Wq, const float* __restrict__ Wk,
    const float* __restrict__ Wv, const float* __restrict__ Wo)
{
    const int z = blockIdx.z;
    if (z < 2){
        const float* src = z ? x2 : x1;
        float* dst       = z ? g_x2 : g_x1;
        const int ng = MROWS*D_MODEL/8;
        for (int gi = blockIdx.x*blockDim.x + threadIdx.x; gi < ng; gi += gridDim.x*blockDim.x){
            float4 lo = ((const float4*)src)[gi*2];
            float4 hi = ((const float4*)src)[gi*2+1];
            float4 o0 = make_float4(to_tf32(lo.x), to_tf32(hi.x), to_tf32(lo.y), to_tf32(hi.y));
            float4 o1 = make_float4(to_tf32(lo.z), to_tf32(hi.z), to_tf32(lo.w), to_tf32(hi.w));
            ((float4*)dst)[gi*2]   = o0;
            ((float4*)dst)[gi*2+1] = o1;
        }
    } else {
        const float* src; float* dst;
        switch (z){
            case 2: src = Wq; dst = g_Wq; break;
            case 3: src = Wk; dst = g_Wk; break;
            case 4: src = Wv; dst = g_Wv; break;
            default:src = Wo; dst = g_Wo; break;
        }
        const int n4 = D_MODEL*D_MODEL/4;
        for (int i = blockIdx.x*blockDim.x + threadIdx.x; i < n4; i += gridDim.x*blockDim.x){
            float4 v = ((const float4*)src)[i];
            v.x = to_tf32(v.x); v.y = to_tf32(v.y);
            v.z = to_tf32(v.z); v.w = to_tf32(v.w);
            ((float4*)dst)[i] = v;
        }
    }
}

// ---------------- tiled tf32 GEMM (R8 winner: cp.async 2-stage) --------------
// C = (A @ W + b) * oscale. A tf32 + k-interleaved; W tf32 plain.
// BM=128 BN=128 BK=32, 256 threads (8 warps as 2x4), warp tile 64x32.
// MODE: 0 = plain f32 out; 1 = tf32 + col-interleave; 2 = tf32 transposed V
// with PLAIN keys (consumed register-direct by attention PV).
#define AS_LD 40            // 40 % 32 == 8 -> float2 A-frag banks conflict-free
#define BS_LD 136           // 136 % 32 == 8 -> B-frag bank (8tg+g): conflict-free
#define AS_SZ (128*AS_LD)   // 5120 floats
#define BS_SZ (32*BS_LD)    // 4352 floats
#define GEMM_SMEM (2*(AS_SZ + BS_SZ)*4)   // 75776 bytes
#define KT32 (D_MODEL/32)

template<int MODE>
__device__ __forceinline__ void gemm_bias(const float* __restrict__ A,
                                          const float* __restrict__ W,
                                          const float* __restrict__ bias,
                                          float* __restrict__ C,
                                          const float oscale)
{
    extern __shared__ float sm[];
    float* As = sm;               // 2 buffers
    float* Bs = sm + 2*AS_SZ;

    const int tid  = threadIdx.x;
    const int lane = tid & 31;
    const int warp = tid >> 5;
    const int g    = lane >> 2;
    const int tg   = lane & 3;
    const int wm   = warp >> 2;   // 0..1
    const int wn   = warp & 3;    // 0..3
    const int bm   = blockIdx.y * 128;
    const int bn   = blockIdx.x * 128;

    float c[4][4][4];
#pragma unroll
    for (int i=0;i<4;i++)
#pragma unroll
        for (int j=0;j<4;j++){ c[i][j][0]=0.f;c[i][j][1]=0.f;c[i][j][2]=0.f;c[i][j][3]=0.f; }

    auto fill = [&](int t, int s){
        float* As_ = As + s*AS_SZ;
        float* Bs_ = Bs + s*BS_SZ;
        const int k0 = t*32;
#pragma unroll
        for (int i=0;i<4;i++){
            int f = tid + i*256;
            cpa16(As_ + (f>>3)*AS_LD + ((f&7)<<2),
                  A + (size_t)(bm + (f>>3))*D_MODEL + k0 + ((f&7)<<2));
            cpa16(Bs_ + (f>>5)*BS_LD + ((f&31)<<2),
                  W + (size_t)(k0 + (f>>5))*D_MODEL + bn + ((f&31)<<2));
        }
        CP_COMMIT();
    };

    fill(0, 0);

    for (int t = 0; t < KT32; ++t){
        CP_WAIT0();
        __syncthreads();
        if (t+1 < KT32) fill(t+1, (t+1)&1);

        const float* Asc = As + (t&1)*AS_SZ;
        const float* Bsc = Bs + (t&1)*BS_SZ;
#pragma unroll
        for (int kt=0;kt<4;kt++){
            unsigned af[4][4], bf[4][2];
#pragma unroll
            for (int i=0;i<4;i++){
                const float* p = Asc + (wm*64 + i*16 + g)*AS_LD + kt*8 + 2*tg;
                float2 v0 = *(const float2*)p;
                float2 v1 = *(const float2*)(p + 8*AS_LD);
                af[i][0]=__float_as_uint(v0.x);
                af[i][1]=__float_as_uint(v1.x);
                af[i][2]=__float_as_uint(v0.y);
                af[i][3]=__float_as_uint(v1.y);
            }
#pragma unroll
            for (int j=0;j<4;j++){
                const float* p = Bsc + (kt*8 + tg)*BS_LD + wn*32 + j*8 + g;
                bf[j][0]=__float_as_uint(p[0]);
                bf[j][1]=__float_as_uint(p[4*BS_LD]);
            }
#pragma unroll
            for (int i=0;i<4;i++)
#pragma unroll
                for (int j=0;j<4;j++)
                    mma8(c[i][j], af[i], bf[j]);
        }
    }
    __syncthreads();

    // epilogue
#pragma unroll
    for (int i=0;i<4;i++){
        const int r0 = bm + wm*64 + i*16 + g;
#pragma unroll
        for (int j=0;j<4;j++){
            const int gb  = bn + wn*32 + j*8;
            const int col = gb + 2*tg;
            const float b0 = bias[col], b1 = bias[col+1];
            float v00=(c[i][j][0]+b0)*oscale, v01=(c[i][j][1]+b1)*oscale;
            float v10=(c[i][j][2]+b0)*oscale, v11=(c[i][j][3]+b1)*oscale;
            if (MODE == 0){
                *(float2*)(C + (size_t)r0*D_MODEL + col)     = make_float2(v00, v01);
                *(float2*)(C + (size_t)(r0+8)*D_MODEL + col) = make_float2(v10, v11);
            } else if (MODE == 1){
                const int pos = ((tg&1)<<2) | (tg>>1);   // q(2tg); q(2tg+1)=pos+2
                C[(size_t)r0*D_MODEL + gb + pos]       = to_tf32(v00);
                C[(size_t)r0*D_MODEL + gb + pos + 2]   = to_tf32(v01);
                C[(size_t)(r0+8)*D_MODEL + gb + pos]   = to_tf32(v10);
                C[(size_t)(r0+8)*D_MODEL + gb + pos+2] = to_tf32(v11);
            } else {
                // transposed V: C[b][dim][key], keys PLAIN
                const int bidx = r0 >> 11;
                const int s0   = r0 & 2047;       // s0 & 7 == g
                const size_t base = ((size_t)bidx*D_MODEL + col)*SEQ;
                C[base + s0]           = to_tf32(v00);
                C[base + SEQ + s0]     = to_tf32(v01);
                C[base + s0 + 8]       = to_tf32(v10);
                C[base + SEQ + s0 + 8] = to_tf32(v11);
            }
        }
    }
}

__global__ void __launch_bounds__(256, 2) qkv_kernel(
    const float* __restrict__ bq, const float* __restrict__ bk,
    const float* __restrict__ bv)
{
    // Q carries 1/sqrt(HDIM)=0.125 (exact pow2, commutes with tf32 rounding).
    if      (blockIdx.z == 0) gemm_bias<1>(g_x1, g_Wq, bq, g_Q, 0.125f);
    else if (blockIdx.z == 1) gemm_bias<1>(g_x2, g_Wk, bk, g_K, 1.0f);
    else                      gemm_bias<2>(g_x2, g_Wv, bv, g_Vt, 1.0f);
}

__global__ void __launch_bounds__(256, 2) oproj_kernel(
    const float* __restrict__ bo, float* __restrict__ out)
{
    gemm_bias<0>(g_ctx, g_Wo, bo, out, 1.0f);
}

// ---------------- flash attention (P kept in registers, no smem round-trip) --
// CTA: 128 q-rows of one (b,h); 8 warps x 16 rows. K/V via cp.async 2-deep ring.
// Q/K dims interleaved; V transposed [dim][key] with PLAIN keys.
// PV contraction slot (kt,tg) <- key kt*8+2tg, (kt,tg+4) <- key kt*8+2tg+1:
// exactly the keys each thread holds in s[kt][*] after QK -> pa built in regs.
#define QP_LD 72   // 72 % 32 == 8 -> float2 frag banks conflict-free
#define K_LD  72
#define V_LD  72
#define KV_BUF (64*K_LD + 64*V_LD)   // 9216 floats per stage
#define ATTN_SMEM ((128*QP_LD + 2*KV_BUF)*4)   // 110592 bytes
#define NT (SEQ/64)

__global__ void __launch_bounds__(256, 2) attn_kernel()
{
    extern __shared__ float sm[];
    float* Qs = sm;                       // 128*QP_LD (prologue only)

    const int tid  = threadIdx.x;
    const int lane = tid & 31;
    const int warp = tid >> 5;
    const int g    = lane >> 2;
    const int tg   = lane & 3;
    const int b    = blockIdx.y >> 4;
    const int h    = blockIdx.y & 15;
    const int q0   = blockIdx.x * 128;

    const float* Kb = g_K  + (size_t)(b*SEQ)*D_MODEL + h*HDIM;
    const float* Vb = g_Vt + ((size_t)(b*D_MODEL) + h*HDIM)*SEQ;  // rows=dims

    const int cr[4] = { (tid)>>4, (tid+256)>>4, (tid+512)>>4, (tid+768)>>4 };
    const int cc    = (tid & 15) << 2;

    {
        float* Ks0 = sm + 128*QP_LD;
        float* Vs0 = Ks0 + 64*K_LD;
#pragma unroll
        for (int i=0;i<4;i++){
            int r = cr[i];
            cpa16(Ks0 + r*K_LD + cc, Kb + (size_t)r*D_MODEL + cc);
            cpa16(Vs0 + r*V_LD + cc, Vb + (size_t)r*SEQ + cc);
        }
        CP_COMMIT();
    }

    const float* Qg = g_Q + (size_t)(b*SEQ + q0)*D_MODEL + h*HDIM;
#pragma unroll
    for (int i=0;i<8;i++){
        int f = tid + i*256;
        int r = f >> 4, c = (f & 15) << 2;
        *(float4*)(Qs + r*QP_LD + c) = *(const float4*)(Qg + (size_t)r*D_MODEL + c);
    }
    __syncthreads();

    unsigned qa[8][4];
#pragma unroll
    for (int kt=0;kt<8;kt++){
        const float* p = Qs + (warp*16 + g)*QP_LD + kt*8 + 2*tg;
        float2 v0 = *(const float2*)p;
        float2 v1 = *(const float2*)(p + 8*QP_LD);
        qa[kt][0]=__float_as_uint(v0.x);
        qa[kt][1]=__float_as_uint(v1.x);
        qa[kt][2]=__float_as_uint(v0.y);
        qa[kt][3]=__float_as_uint(v1.y);
    }

    float ctx[8][4];
#pragma unroll
    for (int n=0;n<8;n++){ ctx[n][0]=0.f;ctx[n][1]=0.f;ctx[n][2]=0.f;ctx[n][3]=0.f; }
    const float NEG = -1e30f;
    float m0=NEG, m1=NEG, l0=0.f, l1=0.f;

    for (int t=0; t<NT; ++t){
        CP_WAIT0();
        __syncthreads();

        if (t+1 < NT){
            float* Ksn = sm + 128*QP_LD + ((t+1)&1)*KV_BUF;
            float* Vsn = Ksn + 64*K_LD;
            const float* Kg = Kb + (size_t)(t+1)*64*D_MODEL;
            const float* Vg = Vb + (t+1)*64;
#pragma unroll
            for (int i=0;i<4;i++){
                int r = cr[i];
                cpa16(Ksn + r*K_LD + cc, Kg + (size_t)r*D_MODEL + cc);
                cpa16(Vsn + r*V_LD + cc, Vg + (size_t)r*SEQ + cc);
            }
            CP_COMMIT();
        }

        const float* Ks = sm + 128*QP_LD + (t&1)*KV_BUF;
        const float* Vs = Ks + 64*K_LD;

        // ---- S = Q @ K^T ----
        float s[8][4];
#pragma unroll
        for (int n=0;n<8;n++){ s[n][0]=0.f;s[n][1]=0.f;s[n][2]=0.f;s[n][3]=0.f; }
#pragma unroll
        for (int nt=0;nt<8;nt++){
#pragma unroll
            for (int kt=0;kt<8;kt++){
                float2 kv = *(const float2*)(Ks + (nt*8 + g)*K_LD + kt*8 + 2*tg);
                unsigned bf[2] = { __float_as_uint(kv.x), __float_as_uint(kv.y) };
                mma8(s[nt], qa[kt], bf);
            }
        }

        // ---- online softmax ----
        float rm0=NEG, rm1=NEG;
#pragma unroll
        for (int n=0;n<8;n++){
            rm0 = fmaxf(rm0, fmaxf(s[n][0], s[n][1]));
            rm1 = fmaxf(rm1, fmaxf(s[n][2], s[n][3]));
        }
        rm0 = fmaxf(rm0, __shfl_xor_sync(0xffffffffu, rm0, 1));
        rm0 = fmaxf(rm0, __shfl_xor_sync(0xffffffffu, rm0, 2));
        rm1 = fmaxf(rm1, __shfl_xor_sync(0xffffffffu, rm1, 1));
        rm1 = fmaxf(rm1, __shfl_xor_sync(0xffffffffu, rm1, 2));
        const float mn0 = fmaxf(m0, rm0), mn1 = fmaxf(m1, rm1);
        const float a0 = __expf(m0 - mn0), a1 = __expf(m1 - mn1);
        float rs0=0.f, rs1=0.f;
#pragma unroll
        for (int n=0;n<8;n++){
            s[n][0]=__expf(s[n][0]-mn0); s[n][1]=__expf(s[n][1]-mn0);
            s[n][2]=__expf(s[n][2]-mn1); s[n][3]=__expf(s[n][3]-mn1);
            rs0 += s[n][0]+s[n][1];
            rs1 += s[n][2]+s[n][3];
        }
        rs0 += __shfl_xor_sync(0xffffffffu, rs0, 1);
        rs0 += __shfl_xor_sync(0xffffffffu, rs0, 2);
        rs1 += __shfl_xor_sync(0xffffffffu, rs1, 1);
        rs1 += __shfl_xor_sync(0xffffffffu, rs1, 2);
        l0 = a0*l0 + rs0;  l1 = a1*l1 + rs1;
        m0 = mn0;          m1 = mn1;
#pragma unroll
        for (int n=0;n<8;n++){
            ctx[n][0]*=a0; ctx[n][1]*=a0; ctx[n][2]*=a1; ctx[n][3]*=a1;
        }

        // ---- P -> tf32 in registers (same values as the old smem path) ----
#pragma unroll
        for (int n=0;n<8;n++){
            s[n][0]=to_tf32(s[n][0]); s[n][1]=to_tf32(s[n][1]);
            s[n][2]=to_tf32(s[n][2]); s[n][3]=to_tf32(s[n][3]);
        }

        // ---- ctx += P @ V : pa direct from registers, V plain-keyed ----
#pragma unroll
        for (int kt=0;kt<8;kt++){
            unsigned pa[4] = { __float_as_uint(s[kt][0]), __float_as_uint(s[kt][2]),
                               __float_as_uint(s[kt][1]), __float_as_uint(s[kt][3]) };
#pragma unroll
            for (int nt=0;nt<8;nt++){
                float2 vv = *(const float2*)(Vs + (nt*8 + g)*V_LD + kt*8 + 2*tg);
                unsigned bf[2] = { __float_as_uint(vv.x), __float_as_uint(vv.y) };
                mma8(ctx[nt], pa, bf);
            }
        }
    }

    // ---- normalize + write ctx tf32 with interleaved cols for oproj ----
    const float il0 = 1.f/l0, il1 = 1.f/l1;
    const int r = b*SEQ + q0 + warp*16 + g;
    const int ppos = ((tg&1)<<2) | (tg>>1);   // q(2tg)
#pragma unroll
    for (int n=0;n<8;n++){
        const int gb = h*HDIM + n*8;
        g_ctx[(size_t)r*D_MODEL + gb + ppos]       = to_tf32(ctx[n][0]*il0);
        g_ctx[(size_t)r*D_MODEL + gb + ppos + 2]   = to_tf32(ctx[n][1]*il0);
        g_ctx[(size_t)(r+8)*D_MODEL + gb + ppos]   = to_tf32(ctx[n][2]*il1);
        g_ctx[(size_t)(r+8)*D_MODEL + gb + ppos+2] = to_tf32(ctx[n][3]*il1);
    }
}

// ---------------- launch ----------------------------------------------------
extern "C" void kernel_launch(void* const* d_in, const int* in_sizes, int n_in,
                              void* d_out, int out_size)
{
    (void)in_sizes; (void)n_in; (void)out_size;
    const float* x1 = (const float*)d_in[0];
    const float* x2 = (const float*)d_in[1];
    const float* Wq = (const float*)d_in[2];
    const float* bq = (const float*)d_in[3];
    const float* Wk = (const float*)d_in[4];
    const float* bk = (const float*)d_in[5];
    const float* Wv = (const float*)d_in[6];
    const float* bv = (const float*)d_in[7];
    const float* Wo = (const float*)d_in[8];
    const float* bo = (const float*)d_in[9];
    float* out = (float*)d_out;

    cudaFuncSetAttribute(qkv_kernel,  cudaFuncAttributeMaxDynamicSharedMemorySize, GEMM_SMEM);
    cudaFuncSetAttribute(oproj_kernel,cudaFuncAttributeMaxDynamicSharedMemorySize, GEMM_SMEM);
    cudaFuncSetAttribute(attn_kernel, cudaFuncAttributeMaxDynamicSharedMemorySize, ATTN_SMEM);

    preround_kernel<<<dim3(1024, 1, 6), 256>>>(x1, x2, Wq, Wk, Wv, Wo);
    qkv_kernel<<<dim3(D_MODEL/128, MROWS/128, 3), 256, GEMM_SMEM>>>(bq, bk, bv);
    attn_kernel<<<dim3(SEQ/128, BATCH*NHEADS), 256, ATTN_SMEM>>>();
    oproj_kernel<<<dim3(D_MODEL/128, MROWS/128), 256, GEMM_SMEM>>>(bo, out);
}